// round 15
// baseline (speedup 1.0000x reference)
#include <cuda_runtime.h>
#include <cuda_bf16.h>

// Device-global scratch (no allocations allowed).
__device__ float    g_P[25 * 112];     // 25 CTA partials: 100 matrix + 10 bias + pad
__device__ float    g_M3[100];         // final composed matrix [out][in] row-major
__device__ float    g_c3[10];          // final composed bias
__device__ unsigned g_ctr1;            // partial arrivals from CTAs 1..24 (self-reset)

#define TPB 256
#define NSTAGE 5
#define STAGE_PAIRS 240                      // 8 warps x 30 pairs
#define STAGE_FLOATS (STAGE_PAIRS * 20)      // 19200 B
#define BAR_FLOATS 256
#define APPLY_SMEM ((BAR_FLOATS + NSTAGE * STAGE_FLOATS) * 4)   // ~97KB -> 2 CTAs/SM

// ---------------------------------------------------------------------------
// PTX helpers.
// ---------------------------------------------------------------------------
__device__ __forceinline__ unsigned smem_u32(const void* p) {
    unsigned r;
    asm("{ .reg .u64 t; cvta.to.shared.u64 t, %1; cvt.u32.u64 %0, t; }"
        : "=r"(r) : "l"(p));
    return r;
}
__device__ __forceinline__ void mbar_init(unsigned addr, unsigned count) {
    asm volatile("mbarrier.init.shared.b64 [%0], %1;" :: "r"(addr), "r"(count) : "memory");
}
__device__ __forceinline__ void mbar_expect_tx(unsigned addr, unsigned bytes) {
    asm volatile("mbarrier.arrive.expect_tx.shared.b64 _, [%0], %1;"
                 :: "r"(addr), "r"(bytes) : "memory");
}
__device__ __forceinline__ void bulk_load(unsigned dst_smem, const void* src_gmem,
                                          unsigned bytes, unsigned mbar) {
    asm volatile("cp.async.bulk.shared::cta.global.mbarrier::complete_tx::bytes "
                 "[%0], [%1], %2, [%3];"
                 :: "r"(dst_smem), "l"(src_gmem), "r"(bytes), "r"(mbar) : "memory");
}
__device__ __forceinline__ void mbar_wait(unsigned addr, unsigned parity) {
    unsigned done;
    asm volatile("{\n\t.reg .pred p;\n\t"
                 "mbarrier.try_wait.parity.acquire.cta.shared::cta.b64 p, [%1], %2;\n\t"
                 "selp.b32 %0, 1, 0, p;\n\t}"
                 : "=r"(done) : "r"(addr), "r"(parity) : "memory");
    while (!done) {
        asm volatile("{\n\t.reg .pred p;\n\t"
                     "mbarrier.try_wait.parity.acquire.cta.shared::cta.b64 p, [%1], %2, 0x989680;\n\t"
                     "selp.b32 %0, 1, 0, p;\n\t}"
                     : "=r"(done) : "r"(addr), "r"(parity) : "memory");
    }
}

// ---------------------------------------------------------------------------
// Fold primitives. Partial layout: 112 floats = [0,100) matrix row-major,
// [100,110) bias, 2 pad. Lane j<10 carries column j; lane 10 carries the bias.
// ---------------------------------------------------------------------------
__device__ __forceinline__ void apply_step(const float* __restrict__ B,
                                           const float* __restrict__ bbias,
                                           int lane, float m[10]) {
    const float2* Br = (const float2*)B;
    float acc[10];
    #pragma unroll
    for (int i = 0; i < 10; ++i) {
        const float2 w0 = Br[i * 5 + 0];
        const float2 w1 = Br[i * 5 + 1];
        const float2 w2 = Br[i * 5 + 2];
        const float2 w3 = Br[i * 5 + 3];
        const float2 w4 = Br[i * 5 + 4];
        float a;
        a = w0.x * m[0];
        a = fmaf(w0.y, m[1], a);
        a = fmaf(w1.x, m[2], a);
        a = fmaf(w1.y, m[3], a);
        a = fmaf(w2.x, m[4], a);
        a = fmaf(w2.y, m[5], a);
        a = fmaf(w3.x, m[6], a);
        a = fmaf(w3.y, m[7], a);
        a = fmaf(w4.x, m[8], a);
        a = fmaf(w4.y, m[9], a);
        acc[i] = a;
    }
    if (lane == 10) {
        #pragma unroll
        for (int i = 0; i < 10; ++i) acc[i] += bbias[i];
    }
    #pragma unroll
    for (int i = 0; i < 10; ++i) m[i] = acc[i];
}

__device__ __forceinline__ void warp_fold_chain(const float* __restrict__ Wsm,
                                                const float* __restrict__ bsm,
                                                int n, int lane, float m[10]) {
    #pragma unroll
    for (int k = 0; k < 10; ++k)
        m[k] = (lane < 10) ? Wsm[k * 10 + lane] : bsm[k];
    #pragma unroll 1
    for (int s = 1; s < n; ++s)
        apply_step(Wsm + s * 100, bsm + s * 10, lane, m);
}

__device__ __forceinline__ void warp_fold2(const float* __restrict__ A,
                                           const float* __restrict__ B,
                                           int lane, float m[10]) {
    #pragma unroll
    for (int k = 0; k < 10; ++k)
        m[k] = (lane < 10) ? A[k * 10 + lane] : A[100 + k];
    apply_step(B, B + 100, lane, m);
}

__device__ __forceinline__ void store_partial(float* __restrict__ D,
                                              const float m[10], int lane) {
    if (lane < 10) {
        #pragma unroll
        for (int k = 0; k < 10; ++k) D[k * 10 + lane] = m[k];
    } else if (lane == 10) {
        #pragma unroll
        for (int k = 0; k < 10; ++k) D[100 + k] = m[k];
    }
}

__device__ __forceinline__ void warp_copy4(float* dst, const float* src,
                                           int nfloats, int lane) {
    const float4* s4 = (const float4*)src;
    float4* d4 = (float4*)dst;
    #pragma unroll 4
    for (int i = lane; i < nfloats / 4; i += 32) d4[i] = s4[i];
}
__device__ __forceinline__ void warp_copy1(float* dst, const float* src,
                                           int nfloats, int lane) {
    for (int i = lane; i < nfloats; i += 32) dst[i] = src[i];
}

// ---------------------------------------------------------------------------
// NODE 1: fold_kernel (grid = 25 x 256), depth-13 tree. Triggers the PDL
// launch of apply_kernel at entry so the two overlap.
// ---------------------------------------------------------------------------
__global__ void __launch_bounds__(TPB) fold_kernel(const float* __restrict__ Ws,
                                                   const float* __restrict__ bs) {
    cudaTriggerProgrammaticLaunchCompletion();   // let apply launch NOW

    __shared__ float SLOT[8][560];    // per-warp: 500 W + 50 b + pad
    __shared__ float PA[8 * 112];
    __shared__ float PB[4 * 112];
    __shared__ float RED[38 * 112];   // CTA0 reduction ping-pong (25 + 13)

    const int tid  = threadIdx.x;
    const int lane = tid & 31;
    const int warp = tid >> 5;
    const int cta  = blockIdx.x;

    // ---- Level 1: warp folds layers [5*(8*cta+warp), +5) ----
    const int chunk = cta * 8 + warp;                  // 0..199
    warp_copy4(SLOT[warp],       Ws + (size_t)chunk * 500, 500, lane);
    warp_copy1(SLOT[warp] + 500, bs + (size_t)chunk * 50,  50,  lane);
    __syncwarp();
    float m[10];
    warp_fold_chain(SLOT[warp], SLOT[warp] + 500, 5, lane, m);
    store_partial(PA + warp * 112, m, lane);
    __syncthreads();

    // ---- Intra-CTA pairwise 8 -> 4 -> 2 -> 1 ----
    if (warp < 4) {
        warp_fold2(PA + (2 * warp) * 112, PA + (2 * warp + 1) * 112, lane, m);
        store_partial(PB + warp * 112, m, lane);
    }
    __syncthreads();
    if (warp < 2) {
        warp_fold2(PB + (2 * warp) * 112, PB + (2 * warp + 1) * 112, lane, m);
        store_partial(PA + warp * 112, m, lane);
    }
    __syncthreads();
    if (warp == 0) {
        warp_fold2(PA, PA + 112, lane, m);
        store_partial(g_P + cta * 112, m, lane);
    }
    __threadfence();
    __syncthreads();

    if (cta != 0) {
        if (tid == 0) atomicAdd(&g_ctr1, 1u);
        return;
    }

    // ---- CTA 0: final pairwise reduce of 25 partials ----
    if (tid == 0) {
        while (*(volatile unsigned*)&g_ctr1 < 24u) __nanosleep(32);
    }
    __syncthreads();
    __threadfence();   // acquire

    float* SA = RED;            // 25 x 112
    float* SB = RED + 25 * 112; // up to 13 x 112
    for (int i = tid; i < 25 * 112; i += TPB) SA[i] = g_P[i];
    __syncthreads();

    float* src = SA;
    float* dst = SB;
    int cnt = 25;
    while (cnt > 1) {
        const int half = cnt >> 1;
        for (int w = warp; w < half; w += 8) {
            float mm[10];
            warp_fold2(src + (2 * w) * 112, src + (2 * w + 1) * 112, lane, mm);
            store_partial(dst + w * 112, mm, lane);
        }
        __syncthreads();
        if (cnt & 1) {
            for (int i = tid; i < 112; i += TPB)
                dst[half * 112 + i] = src[(cnt - 1) * 112 + i];
            __syncthreads();
        }
        cnt = half + (cnt & 1);
        float* tp = src; src = dst; dst = tp;
    }
    for (int i = tid; i < 100; i += TPB) g_M3[i] = src[i];
    if (tid < 10) g_c3[tid] = src[100 + tid];
    if (tid == 0) g_ctr1 = 0;   // replay-safe reset (after final use)
}

// ---------------------------------------------------------------------------
// NODE 2: apply_kernel (PDL consumer). Issues its TMA prologue (x-only),
// THEN waits for the fold grid via cudaGridDependencySynchronize, then
// streams: out[r] = x[r] @ M^T + c.
// ---------------------------------------------------------------------------
__global__ void __launch_bounds__(TPB, 2) apply_kernel(const float* __restrict__ x,
                                                       float* __restrict__ out,
                                                       long long pairs,
                                                       long long rows) {
    extern __shared__ float SH[];
    const int tid = threadIdx.x;

    unsigned bar[NSTAGE];
    #pragma unroll
    for (int s = 0; s < NSTAGE; ++s) bar[s] = smem_u32(&SH[s * 2]);
    if (tid == 0) {
        #pragma unroll
        for (int s = 0; s < NSTAGE; ++s) mbar_init(bar[s], 1);
    }
    __syncthreads();

    const long long tiles   = (pairs + STAGE_PAIRS - 1) / STAGE_PAIRS;
    const long long gstride = gridDim.x;
    const long long cta     = blockIdx.x;

    // Prologue: fill all stages (depends only on x; overlaps the fold).
    if (tid == 0) {
        #pragma unroll
        for (int s = 0; s < NSTAGE; ++s) {
            const long long t = cta + (long long)s * gstride;
            if (t < tiles) {
                const long long pbase = t * STAGE_PAIRS;
                const unsigned np = (unsigned)((pairs - pbase < STAGE_PAIRS)
                                                 ? (pairs - pbase) : STAGE_PAIRS);
                mbar_expect_tx(bar[s], np * 80u);
                bulk_load(smem_u32(&SH[BAR_FLOATS + s * STAGE_FLOATS]),
                          x + pbase * 20, np * 80u, bar[s]);
            }
        }
    }

    // Wait for the fold grid (completion + memory flush), then read M/c.
    cudaGridDependencySynchronize();

    // Per-lane constants: phase = lane%5 -> 4 consecutive output floats.
    const int lane  = tid & 31;
    const int warp  = tid >> 5;
    const int phase = lane % 5;
    const int lp    = lane / 5;              // 5-lane group (0..5; 6 inactive)
    const bool active = (lane < 30);
    const int offA = (phase >= 3) ? 10 : 0;  // source row for outputs w=0,1
    const int offB = (phase >= 2) ? 10 : 0;  // source row for outputs w=2,3

    float mw[40], cw[4];
    #pragma unroll
    for (int w = 0; w < 4; ++w) {
        const int jw = (4 * phase + w) % 10;
        cw[w] = __ldg(&g_c3[jw]);
        #pragma unroll
        for (int k = 0; k < 10; ++k) mw[w * 10 + k] = __ldg(&g_M3[jw * 10 + k]);
    }

    float4* out4 = (float4*)out;

    long long i = 0;
    #pragma unroll 1
    for (long long t = cta; t < tiles; t += gstride, ++i) {
        const int s = (int)(i % NSTAGE);
        const unsigned parity = (unsigned)((i / NSTAGE) & 1);
        mbar_wait(bar[s], parity);

        const float* st = &SH[BAR_FLOATS + s * STAGE_FLOATS];
        const long long tb = t * STAGE_PAIRS;

        #pragma unroll
        for (int it = 0; it < 5; ++it) {
            const int p = warp * 30 + it * 6 + lp;
            const long long gp = tb + p;
            if (active && gp < pairs) {
                const float2* rA = (const float2*)(st + p * 20 + offA);
                const float2* rB = (const float2*)(st + p * 20 + offB);
                float o0 = cw[0], o1 = cw[1], o2 = cw[2], o3 = cw[3];
                #pragma unroll
                for (int kk = 0; kk < 5; ++kk) {
                    const float2 a = rA[kk];
                    const float2 b = rB[kk];
                    o0 = fmaf(mw[2 * kk],          a.x, o0);
                    o0 = fmaf(mw[2 * kk + 1],      a.y, o0);
                    o1 = fmaf(mw[10 + 2 * kk],     a.x, o1);
                    o1 = fmaf(mw[10 + 2 * kk + 1], a.y, o1);
                    o2 = fmaf(mw[20 + 2 * kk],     b.x, o2);
                    o2 = fmaf(mw[20 + 2 * kk + 1], b.y, o2);
                    o3 = fmaf(mw[30 + 2 * kk],     b.x, o3);
                    o3 = fmaf(mw[30 + 2 * kk + 1], b.y, o3);
                }
                out4[gp * 5 + phase] = make_float4(o0, o1, o2, o3);
            }
        }

        __syncthreads();   // all warps done reading stage s
        const long long tn = t + (long long)NSTAGE * gstride;
        if (tn < tiles && tid == 0) {
            const long long pbase = tn * STAGE_PAIRS;
            const unsigned np = (unsigned)((pairs - pbase < STAGE_PAIRS)
                                             ? (pairs - pbase) : STAGE_PAIRS);
            mbar_expect_tx(bar[s], np * 80u);
            bulk_load(smem_u32(&SH[BAR_FLOATS + s * STAGE_FLOATS]),
                      x + pbase * 20, np * 80u, bar[s]);
        }
    }

    // Odd-row tail (rows is even here; kept for safety).
    if ((rows & 1LL) && blockIdx.x == 0 && tid == 0) {
        const long long r = rows - 1;
        const float* xr = x + r * 10;
        float h[10];
        #pragma unroll
        for (int k = 0; k < 10; ++k) h[k] = xr[k];
        float* orow = out + r * 10;
        #pragma unroll
        for (int j = 0; j < 10; ++j) {
            float a = __ldg(&g_c3[j]);
            #pragma unroll
            for (int k = 0; k < 10; ++k) a += h[k] * __ldg(&g_M3[j * 10 + k]);
            orow[j] = a;
        }
    }
}

extern "C" void kernel_launch(void* const* d_in, const int* in_sizes, int n_in,
                              void* d_out, int out_size) {
    // Identify inputs by element count: x=BATCH*10, Ws=1000*100, bs=1000*10.
    const float* x  = nullptr;
    const float* Ws = nullptr;
    const float* bs = nullptr;
    long long x_elems = 0;
    for (int i = 0; i < n_in; ++i) {
        if (in_sizes[i] == 1000 * 100) {
            Ws = (const float*)d_in[i];
        } else if (in_sizes[i] == 1000 * 10) {
            bs = (const float*)d_in[i];
        } else {
            x = (const float*)d_in[i];
            x_elems = in_sizes[i];
        }
    }
    const long long rows  = x_elems / 10;
    const long long pairs = rows >> 1;

    static int smem_set = 0;
    if (!smem_set) {
        cudaFuncSetAttribute(apply_kernel,
                             cudaFuncAttributeMaxDynamicSharedMemorySize, APPLY_SMEM);
        smem_set = 1;
    }

    // Node 1: fast fold (triggers PDL completion at entry).
    fold_kernel<<<25, TPB>>>(Ws, bs);

    // Node 2: apply, PDL-chained so it launches while the fold runs.
    cudaLaunchConfig_t cfg = {};
    cfg.gridDim        = dim3(296, 1, 1);
    cfg.blockDim       = dim3(TPB, 1, 1);
    cfg.dynamicSmemBytes = APPLY_SMEM;
    cfg.stream         = 0;
    cudaLaunchAttribute attrs[1];
    attrs[0].id = cudaLaunchAttributeProgrammaticStreamSerialization;
    attrs[0].val.programmaticStreamSerializationAllowed = 1;
    cfg.attrs    = attrs;
    cfg.numAttrs = 1;
    cudaLaunchKernelEx(&cfg, apply_kernel, x, (float*)d_out, pairs, rows);
}

// round 16
// speedup vs baseline: 1.0114x; 1.0114x over previous
#include <cuda_runtime.h>
#include <cuda_bf16.h>

// Device-global scratch (no allocations allowed).
__device__ float    g_P[25 * 112];     // 25 CTA partials: 100 matrix + 10 bias + pad
__device__ float    g_M3[100];         // final composed matrix [out][in] row-major
__device__ float    g_c3[10];          // final composed bias
__device__ unsigned g_ctr1;            // partial arrivals from CTAs 1..24 (self-reset)

#define TPB 256
#define NSTAGE 3
#define STAGE_PAIRS 240                      // 8 warps x 30 pairs
#define STAGE_FLOATS (STAGE_PAIRS * 20)      // 19200 B
#define BAR_FLOATS 256
#define APPLY_SMEM ((BAR_FLOATS + NSTAGE * STAGE_FLOATS) * 4)   // 58.6KB -> 3 CTAs/SM

// ---------------------------------------------------------------------------
// PTX helpers.
// ---------------------------------------------------------------------------
__device__ __forceinline__ unsigned smem_u32(const void* p) {
    unsigned r;
    asm("{ .reg .u64 t; cvta.to.shared.u64 t, %1; cvt.u32.u64 %0, t; }"
        : "=r"(r) : "l"(p));
    return r;
}
__device__ __forceinline__ void mbar_init(unsigned addr, unsigned count) {
    asm volatile("mbarrier.init.shared.b64 [%0], %1;" :: "r"(addr), "r"(count) : "memory");
}
__device__ __forceinline__ void mbar_expect_tx(unsigned addr, unsigned bytes) {
    asm volatile("mbarrier.arrive.expect_tx.shared.b64 _, [%0], %1;"
                 :: "r"(addr), "r"(bytes) : "memory");
}
__device__ __forceinline__ void bulk_load(unsigned dst_smem, const void* src_gmem,
                                          unsigned bytes, unsigned mbar) {
    asm volatile("cp.async.bulk.shared::cta.global.mbarrier::complete_tx::bytes "
                 "[%0], [%1], %2, [%3];"
                 :: "r"(dst_smem), "l"(src_gmem), "r"(bytes), "r"(mbar) : "memory");
}
__device__ __forceinline__ void mbar_wait(unsigned addr, unsigned parity) {
    unsigned done;
    asm volatile("{\n\t.reg .pred p;\n\t"
                 "mbarrier.try_wait.parity.acquire.cta.shared::cta.b64 p, [%1], %2;\n\t"
                 "selp.b32 %0, 1, 0, p;\n\t}"
                 : "=r"(done) : "r"(addr), "r"(parity) : "memory");
    while (!done) {
        asm volatile("{\n\t.reg .pred p;\n\t"
                     "mbarrier.try_wait.parity.acquire.cta.shared::cta.b64 p, [%1], %2, 0x989680;\n\t"
                     "selp.b32 %0, 1, 0, p;\n\t}"
                     : "=r"(done) : "r"(addr), "r"(parity) : "memory");
    }
}

// ---------------------------------------------------------------------------
// Fold primitives. Partial layout: 112 floats = [0,100) matrix row-major,
// [100,110) bias, 2 pad. Lane j<10 carries column j; lane 10 carries the bias.
// ---------------------------------------------------------------------------
__device__ __forceinline__ void apply_step(const float* __restrict__ B,
                                           const float* __restrict__ bbias,
                                           int lane, float m[10]) {
    const float2* Br = (const float2*)B;
    float acc[10];
    #pragma unroll
    for (int i = 0; i < 10; ++i) {
        const float2 w0 = Br[i * 5 + 0];
        const float2 w1 = Br[i * 5 + 1];
        const float2 w2 = Br[i * 5 + 2];
        const float2 w3 = Br[i * 5 + 3];
        const float2 w4 = Br[i * 5 + 4];
        float a;
        a = w0.x * m[0];
        a = fmaf(w0.y, m[1], a);
        a = fmaf(w1.x, m[2], a);
        a = fmaf(w1.y, m[3], a);
        a = fmaf(w2.x, m[4], a);
        a = fmaf(w2.y, m[5], a);
        a = fmaf(w3.x, m[6], a);
        a = fmaf(w3.y, m[7], a);
        a = fmaf(w4.x, m[8], a);
        a = fmaf(w4.y, m[9], a);
        acc[i] = a;
    }
    if (lane == 10) {
        #pragma unroll
        for (int i = 0; i < 10; ++i) acc[i] += bbias[i];
    }
    #pragma unroll
    for (int i = 0; i < 10; ++i) m[i] = acc[i];
}

__device__ __forceinline__ void warp_fold_chain(const float* __restrict__ Wsm,
                                                const float* __restrict__ bsm,
                                                int n, int lane, float m[10]) {
    #pragma unroll
    for (int k = 0; k < 10; ++k)
        m[k] = (lane < 10) ? Wsm[k * 10 + lane] : bsm[k];
    #pragma unroll 1
    for (int s = 1; s < n; ++s)
        apply_step(Wsm + s * 100, bsm + s * 10, lane, m);
}

__device__ __forceinline__ void warp_fold2(const float* __restrict__ A,
                                           const float* __restrict__ B,
                                           int lane, float m[10]) {
    #pragma unroll
    for (int k = 0; k < 10; ++k)
        m[k] = (lane < 10) ? A[k * 10 + lane] : A[100 + k];
    apply_step(B, B + 100, lane, m);
}

__device__ __forceinline__ void store_partial(float* __restrict__ D,
                                              const float m[10], int lane) {
    if (lane < 10) {
        #pragma unroll
        for (int k = 0; k < 10; ++k) D[k * 10 + lane] = m[k];
    } else if (lane == 10) {
        #pragma unroll
        for (int k = 0; k < 10; ++k) D[100 + k] = m[k];
    }
}

__device__ __forceinline__ void warp_copy4(float* dst, const float* src,
                                           int nfloats, int lane) {
    const float4* s4 = (const float4*)src;
    float4* d4 = (float4*)dst;
    #pragma unroll 4
    for (int i = lane; i < nfloats / 4; i += 32) d4[i] = s4[i];
}
__device__ __forceinline__ void warp_copy1(float* dst, const float* src,
                                           int nfloats, int lane) {
    for (int i = lane; i < nfloats; i += 32) dst[i] = src[i];
}

// ---------------------------------------------------------------------------
// NODE 1: fold_kernel (grid = 25 x 256), depth-13 tree (R14-proven).
// ---------------------------------------------------------------------------
__global__ void __launch_bounds__(TPB) fold_kernel(const float* __restrict__ Ws,
                                                   const float* __restrict__ bs) {
    __shared__ float SLOT[8][560];    // per-warp: 500 W + 50 b + pad
    __shared__ float PA[8 * 112];
    __shared__ float PB[4 * 112];
    __shared__ float RED[38 * 112];   // CTA0 reduction ping-pong (25 + 13)

    const int tid  = threadIdx.x;
    const int lane = tid & 31;
    const int warp = tid >> 5;
    const int cta  = blockIdx.x;

    // ---- Level 1: warp folds layers [5*(8*cta+warp), +5) ----
    const int chunk = cta * 8 + warp;                  // 0..199
    warp_copy4(SLOT[warp],       Ws + (size_t)chunk * 500, 500, lane);
    warp_copy1(SLOT[warp] + 500, bs + (size_t)chunk * 50,  50,  lane);
    __syncwarp();
    float m[10];
    warp_fold_chain(SLOT[warp], SLOT[warp] + 500, 5, lane, m);
    store_partial(PA + warp * 112, m, lane);
    __syncthreads();

    // ---- Intra-CTA pairwise 8 -> 4 -> 2 -> 1 ----
    if (warp < 4) {
        warp_fold2(PA + (2 * warp) * 112, PA + (2 * warp + 1) * 112, lane, m);
        store_partial(PB + warp * 112, m, lane);
    }
    __syncthreads();
    if (warp < 2) {
        warp_fold2(PB + (2 * warp) * 112, PB + (2 * warp + 1) * 112, lane, m);
        store_partial(PA + warp * 112, m, lane);
    }
    __syncthreads();
    if (warp == 0) {
        warp_fold2(PA, PA + 112, lane, m);
        store_partial(g_P + cta * 112, m, lane);
    }
    __threadfence();
    __syncthreads();

    if (cta != 0) {
        if (tid == 0) atomicAdd(&g_ctr1, 1u);
        return;
    }

    // ---- CTA 0: final pairwise reduce of 25 partials ----
    if (tid == 0) {
        while (*(volatile unsigned*)&g_ctr1 < 24u) __nanosleep(32);
    }
    __syncthreads();
    __threadfence();   // acquire

    float* SA = RED;            // 25 x 112
    float* SB = RED + 25 * 112; // up to 13 x 112
    for (int i = tid; i < 25 * 112; i += TPB) SA[i] = g_P[i];
    __syncthreads();

    float* src = SA;
    float* dst = SB;
    int cnt = 25;
    while (cnt > 1) {
        const int half = cnt >> 1;
        for (int w = warp; w < half; w += 8) {
            float mm[10];
            warp_fold2(src + (2 * w) * 112, src + (2 * w + 1) * 112, lane, mm);
            store_partial(dst + w * 112, mm, lane);
        }
        __syncthreads();
        if (cnt & 1) {
            for (int i = tid; i < 112; i += TPB)
                dst[half * 112 + i] = src[(cnt - 1) * 112 + i];
            __syncthreads();
        }
        cnt = half + (cnt & 1);
        float* tp = src; src = dst; dst = tp;
    }
    for (int i = tid; i < 100; i += TPB) g_M3[i] = src[i];
    if (tid < 10) g_c3[tid] = src[100 + tid];
    if (tid == 0) g_ctr1 = 0;   // replay-safe reset (after final use)
}

// ---------------------------------------------------------------------------
// NODE 2: apply_kernel — same proven loop, now 3 CTAs/SM (24 warps/SM):
// NSTAGE=3, smem 58.6KB, regs capped at 84 via launch_bounds(256,3).
// ---------------------------------------------------------------------------
__global__ void __launch_bounds__(TPB, 3) apply_kernel(const float* __restrict__ x,
                                                       float* __restrict__ out,
                                                       long long pairs,
                                                       long long rows) {
    extern __shared__ float SH[];
    const int tid = threadIdx.x;

    unsigned bar[NSTAGE];
    #pragma unroll
    for (int s = 0; s < NSTAGE; ++s) bar[s] = smem_u32(&SH[s * 2]);
    if (tid == 0) {
        #pragma unroll
        for (int s = 0; s < NSTAGE; ++s) mbar_init(bar[s], 1);
    }
    __syncthreads();

    const long long tiles   = (pairs + STAGE_PAIRS - 1) / STAGE_PAIRS;
    const long long gstride = gridDim.x;
    const long long cta     = blockIdx.x;

    // Prologue: fill all stages.
    if (tid == 0) {
        #pragma unroll
        for (int s = 0; s < NSTAGE; ++s) {
            const long long t = cta + (long long)s * gstride;
            if (t < tiles) {
                const long long pbase = t * STAGE_PAIRS;
                const unsigned np = (unsigned)((pairs - pbase < STAGE_PAIRS)
                                                 ? (pairs - pbase) : STAGE_PAIRS);
                mbar_expect_tx(bar[s], np * 80u);
                bulk_load(smem_u32(&SH[BAR_FLOATS + s * STAGE_FLOATS]),
                          x + pbase * 20, np * 80u, bar[s]);
            }
        }
    }

    // Per-lane constants: phase = lane%5 -> 4 consecutive output floats.
    const int lane  = tid & 31;
    const int warp  = tid >> 5;
    const int phase = lane % 5;
    const int lp    = lane / 5;              // 5-lane group (0..5; 6 inactive)
    const bool active = (lane < 30);
    const int offA = (phase >= 3) ? 10 : 0;  // source row for outputs w=0,1
    const int offB = (phase >= 2) ? 10 : 0;  // source row for outputs w=2,3

    float mw[40], cw[4];
    #pragma unroll
    for (int w = 0; w < 4; ++w) {
        const int jw = (4 * phase + w) % 10;
        cw[w] = __ldg(&g_c3[jw]);
        #pragma unroll
        for (int k = 0; k < 10; ++k) mw[w * 10 + k] = __ldg(&g_M3[jw * 10 + k]);
    }

    float4* out4 = (float4*)out;

    long long i = 0;
    #pragma unroll 1
    for (long long t = cta; t < tiles; t += gstride, ++i) {
        const int s = (int)(i % NSTAGE);
        const unsigned parity = (unsigned)((i / NSTAGE) & 1);
        mbar_wait(bar[s], parity);

        const float* st = &SH[BAR_FLOATS + s * STAGE_FLOATS];
        const long long tb = t * STAGE_PAIRS;

        #pragma unroll
        for (int it = 0; it < 5; ++it) {
            const int p = warp * 30 + it * 6 + lp;
            const long long gp = tb + p;
            if (active && gp < pairs) {
                const float2* rA = (const float2*)(st + p * 20 + offA);
                const float2* rB = (const float2*)(st + p * 20 + offB);
                float o0 = cw[0], o1 = cw[1], o2 = cw[2], o3 = cw[3];
                #pragma unroll
                for (int kk = 0; kk < 5; ++kk) {
                    const float2 a = rA[kk];
                    const float2 b = rB[kk];
                    o0 = fmaf(mw[2 * kk],          a.x, o0);
                    o0 = fmaf(mw[2 * kk + 1],      a.y, o0);
                    o1 = fmaf(mw[10 + 2 * kk],     a.x, o1);
                    o1 = fmaf(mw[10 + 2 * kk + 1], a.y, o1);
                    o2 = fmaf(mw[20 + 2 * kk],     b.x, o2);
                    o2 = fmaf(mw[20 + 2 * kk + 1], b.y, o2);
                    o3 = fmaf(mw[30 + 2 * kk],     b.x, o3);
                    o3 = fmaf(mw[30 + 2 * kk + 1], b.y, o3);
                }
                out4[gp * 5 + phase] = make_float4(o0, o1, o2, o3);
            }
        }

        __syncthreads();   // all warps done reading stage s
        const long long tn = t + (long long)NSTAGE * gstride;
        if (tn < tiles && tid == 0) {
            const long long pbase = tn * STAGE_PAIRS;
            const unsigned np = (unsigned)((pairs - pbase < STAGE_PAIRS)
                                             ? (pairs - pbase) : STAGE_PAIRS);
            mbar_expect_tx(bar[s], np * 80u);
            bulk_load(smem_u32(&SH[BAR_FLOATS + s * STAGE_FLOATS]),
                      x + pbase * 20, np * 80u, bar[s]);
        }
    }

    // Odd-row tail (rows is even here; kept for safety).
    if ((rows & 1LL) && blockIdx.x == 0 && tid == 0) {
        const long long r = rows - 1;
        const float* xr = x + r * 10;
        float h[10];
        #pragma unroll
        for (int k = 0; k < 10; ++k) h[k] = xr[k];
        float* orow = out + r * 10;
        #pragma unroll
        for (int j = 0; j < 10; ++j) {
            float a = __ldg(&g_c3[j]);
            #pragma unroll
            for (int k = 0; k < 10; ++k) a += h[k] * __ldg(&g_M3[j * 10 + k]);
            orow[j] = a;
        }
    }
}

extern "C" void kernel_launch(void* const* d_in, const int* in_sizes, int n_in,
                              void* d_out, int out_size) {
    // Identify inputs by element count: x=BATCH*10, Ws=1000*100, bs=1000*10.
    const float* x  = nullptr;
    const float* Ws = nullptr;
    const float* bs = nullptr;
    long long x_elems = 0;
    for (int i = 0; i < n_in; ++i) {
        if (in_sizes[i] == 1000 * 100) {
            Ws = (const float*)d_in[i];
        } else if (in_sizes[i] == 1000 * 10) {
            bs = (const float*)d_in[i];
        } else {
            x = (const float*)d_in[i];
            x_elems = in_sizes[i];
        }
    }
    const long long rows  = x_elems / 10;
    const long long pairs = rows >> 1;

    // Node 1: fast fold (depth-13 tree, 25 CTAs).
    fold_kernel<<<25, TPB>>>(Ws, bs);

    // Node 2: apply at 3 CTAs/SM (444 CTAs, 58.6KB smem each, 24 warps/SM).
    static int smem_set = 0;
    if (!smem_set) {
        cudaFuncSetAttribute(apply_kernel,
                             cudaFuncAttributeMaxDynamicSharedMemorySize, APPLY_SMEM);
        smem_set = 1;
    }
    apply_kernel<<<444, TPB, APPLY_SMEM>>>(x, (float*)d_out, pairs, rows);
}